// round 1
// baseline (speedup 1.0000x reference)
#include <cuda_runtime.h>
#include <math.h>

#define PS 16
#define PH 64
#define PW 64
#define NPATCH (PH*PW)
#define NB 32
#define IH 1024
#define IW 1024

// Scratch (no device allocation allowed)
__device__ float g_qual [NB*NPATCH];
__device__ float g_pmean[NB*NPATCH];
__device__ int   g_code [NPATCH];
__device__ float g_scale[NPATCH];
__device__ float g_mpp  [NPATCH];

// ---------------------------------------------------------------------------
// Kernel 1: per-(batch, patch) quality + mean.
// Grid: (4, 64, 32) = (x-quarter, patch-row, batch). Block: 256 threads.
// Each thread owns one column of a 16x256 strip (fully coalesced rows),
// then half-warp (=one patch) shuffle reduction.
// ---------------------------------------------------------------------------
__global__ void stats_kernel(const float* __restrict__ img) {
    const int tx = threadIdx.x;
    const int x  = blockIdx.x * 256 + tx;
    const int sy = blockIdx.y;           // patch row
    const int b  = blockIdx.z;

    const float* base = img + ((size_t)b * IH + (size_t)sy * PS) * IW + x;

    float s = 0.f, ss = 0.f;
#pragma unroll
    for (int y = 0; y < PS; ++y) {
        float v = base[(size_t)y * IW];
        s  += v;
        ss = fmaf(v, v, ss);
    }
    // reduce across the 16 lanes of each patch (half-warp)
#pragma unroll
    for (int off = 8; off >= 1; off >>= 1) {
        s  += __shfl_down_sync(0xffffffffu, s,  off, 16);
        ss += __shfl_down_sync(0xffffffffu, ss, off, 16);
    }
    if ((tx & 15) == 0) {
        float mean = s * (1.0f / 256.0f);
        float var  = (ss - s * s * (1.0f / 256.0f)) * (1.0f / 255.0f); // ddof=1
        var = fmaxf(var, 0.0f);
        float std_ = sqrtf(var);
        float iq   = 1.0f - 2.0f * fabsf(mean - 0.5f);
        float quality = (std_ + iq + var) * (1.0f / 3.0f);
        int px = x >> 4;                 // patch col 0..63
        int p  = sy * PW + px;
        g_qual [b * NPATCH + p] = quality;
        g_pmean[b * NPATCH + p] = mean;
    }
}

// ---------------------------------------------------------------------------
// Kernel 2: per-patch code/scale/mpp. 4096 threads, deterministic reduction
// over batch (strided loads are coalesced across consecutive p).
// ---------------------------------------------------------------------------
__global__ void code_kernel(const float* __restrict__ r_strong,
                            const float* __restrict__ r_drop,
                            const float* __restrict__ r_else,
                            const float* __restrict__ bright_f,
                            const float* __restrict__ contrast_f,
                            const float* __restrict__ slight_f,
                            const int*   __restrict__ aug_choice,
                            const int*   __restrict__ slight_choice) {
    int p = blockIdx.x * 256 + threadIdx.x;
    if (p >= NPATCH) return;

    float q = 0.f, m = 0.f;
#pragma unroll
    for (int b = 0; b < NB; ++b) {
        q += g_qual [b * NPATCH + p];
        m += g_pmean[b * NPATCH + p];
    }
    q *= (1.0f / NB);
    m *= (1.0f / NB);

    bool low    = q < 0.7f;
    bool strong = low  && (r_strong[p] < 0.8f);
    bool drop   = low  && (q < 0.3f) && (r_drop[p] < 0.1f);
    bool els    = !low && (r_else[p] < 0.3f);

    int code = 0;
    if (strong) code = aug_choice[p] + 1;      // 1..4
    if (els)    code = slight_choice[p] + 5;   // 5..6
    if (drop)   code = 7;

    float scale = 0.f;
    if      (code == 1) scale = 0.1f;
    else if (code == 3) scale = bright_f[p];
    else if (code == 4) scale = contrast_f[p];
    else if (code == 5) scale = 0.05f;
    else if (code == 6) scale = slight_f[p];

    g_code [p] = code;
    g_scale[p] = scale;
    g_mpp  [p] = m;
}

// ---------------------------------------------------------------------------
// Kernel 3: apply augmentation. Same strip decomposition as kernel 1.
// img is staged in smem so the 3x3 per-patch blur is a pure smem op; noise is
// only read for patches coded 1/5 (saves most of that 128 MB stream).
// ---------------------------------------------------------------------------
__global__ void apply_kernel(const float* __restrict__ img,
                             const float* __restrict__ noise,
                             float* __restrict__ out) {
    __shared__ float tile[PS][256];
    __shared__ int   s_code[16];
    __shared__ float s_scale[16];
    __shared__ float s_mpp[16];

    const int tx = threadIdx.x;
    const int x  = blockIdx.x * 256 + tx;
    const int sy = blockIdx.y;
    const int b  = blockIdx.z;

    const size_t base = ((size_t)b * IH + (size_t)sy * PS) * IW + x;

#pragma unroll
    for (int y = 0; y < PS; ++y)
        tile[y][tx] = img[base + (size_t)y * IW];

    if (tx < 16) {
        int p = sy * PW + blockIdx.x * 16 + tx;
        s_code [tx] = g_code [p];
        s_scale[tx] = g_scale[p];
        s_mpp  [tx] = g_mpp  [p];
    }
    __syncthreads();

    const int   pp    = tx >> 4;           // local patch 0..15
    const int   lx    = tx & 15;           // col within patch
    const int   code  = s_code[pp];
    const float scale = s_scale[pp];
    const float mpp   = s_mpp[pp];

#pragma unroll
    for (int y = 0; y < PS; ++y) {
        float v = tile[y][tx];
        float r;
        if (code == 0) {
            r = v;
        } else if (code == 7) {
            r = 0.0f;
        } else if (code == 2) {
            // 3x3 avg with zero padding confined to the patch
            float sum = 0.f;
#pragma unroll
            for (int dy = -1; dy <= 1; ++dy) {
                int yy = y + dy;
                if (yy < 0 || yy >= PS) continue;
#pragma unroll
                for (int dx = -1; dx <= 1; ++dx) {
                    int lxx = lx + dx;
                    if (lxx < 0 || lxx >= PS) continue;
                    sum += tile[yy][tx + dx];
                }
            }
            r = sum * (1.0f / 9.0f);
        } else if (code == 1 || code == 5) {
            float nv = noise[base + (size_t)y * IW];
            r = fminf(fmaxf(fmaf(nv, scale, v), 0.0f), 1.0f);
        } else if (code == 3 || code == 6) {
            r = fminf(fmaxf(v * scale, 0.0f), 1.0f);
        } else { // code == 4 (contrast)
            r = fminf(fmaxf(fmaf(v - mpp, scale, mpp), 0.0f), 1.0f);
        }
        out[base + (size_t)y * IW] = r;
    }
}

extern "C" void kernel_launch(void* const* d_in, const int* in_sizes, int n_in,
                              void* d_out, int out_size) {
    const float* img           = (const float*)d_in[0];
    const float* noise         = (const float*)d_in[1];
    const float* r_strong      = (const float*)d_in[2];
    const float* r_drop        = (const float*)d_in[3];
    const float* r_else        = (const float*)d_in[4];
    const float* bright_f      = (const float*)d_in[5];
    const float* contrast_f    = (const float*)d_in[6];
    const float* slight_f      = (const float*)d_in[7];
    const int*   aug_choice    = (const int*)d_in[8];
    const int*   slight_choice = (const int*)d_in[9];
    float* out = (float*)d_out;

    dim3 grid(IW / 256, IH / PS, NB);   // (4, 64, 32)
    stats_kernel<<<grid, 256>>>(img);
    code_kernel<<<NPATCH / 256, 256>>>(r_strong, r_drop, r_else,
                                       bright_f, contrast_f, slight_f,
                                       aug_choice, slight_choice);
    apply_kernel<<<grid, 256>>>(img, noise, out);
}